// round 14
// baseline (speedup 1.0000x reference)
#include <cuda_runtime.h>

#define HW   262144            // 512*512
#define NB   8
#define NC   64
#define G2   32
#define NC2  (G2*G2*G2)        // 32768 cells
#define EPS  1e-4f
#define TPB  256
#define GRID 760               // persistent: 5 CTAs/SM * 152 SMs

// Per-cell: single winning color id (0..63) if the cell is "pure", else 255.
__device__ unsigned char g_pure[NC2];                   // 32KB
// Candidate bitmask for boundary cells (bit k => color k may win). L2-resident.
__device__ uint2 g_mask32[NC2];                         // 256KB

// ---------------- LUT build: warp per cell, ballot-based ----------------
__global__ void build_lut(const float* __restrict__ pal)
{
    __shared__ float3 spal[NC];
    if (threadIdx.x < NC)
        spal[threadIdx.x] = make_float3(pal[3*threadIdx.x],
                                        pal[3*threadIdx.x+1],
                                        pal[3*threadIdx.x+2]);
    __syncthreads();

    int cell = (blockIdx.x * TPB + threadIdx.x) >> 5;   // one cell per warp
    int lane = threadIdx.x & 31;
    if (cell >= NC2) return;

    int cx = (cell >> 10) & 31, cy = (cell >> 5) & 31, cz = cell & 31;
    const float inv = 1.0f / G2;
    float lox = cx * inv, hix = lox + inv;
    float loy = cy * inv, hiy = loy + inv;
    float loz = cz * inv, hiz = loz + inv;

    float3 cA = spal[lane], cB = spal[lane + 32];       // colors lane, lane+32

    // thr = min over colors of (max sq distance from anywhere in the box)
    float dxA = fmaxf(cA.x - lox, hix - cA.x);
    float dyA = fmaxf(cA.y - loy, hiy - cA.y);
    float dzA = fmaxf(cA.z - loz, hiz - cA.z);
    float mA  = fmaf(dxA,dxA, fmaf(dyA,dyA, dzA*dzA));
    float dxB = fmaxf(cB.x - lox, hix - cB.x);
    float dyB = fmaxf(cB.y - loy, hiy - cB.y);
    float dzB = fmaxf(cB.z - loz, hiz - cB.z);
    float mB  = fmaf(dxB,dxB, fmaf(dyB,dyB, dzB*dzB));
    float thr = fminf(mA, mB);
    #pragma unroll
    for (int o = 16; o > 0; o >>= 1)
        thr = fminf(thr, __shfl_xor_sync(0xffffffffu, thr, o));
    thr += EPS;   // margin >> fp ordering noise in BOTH implementations

    // candidate test: nearest-point box distance <= thr
    float nxA = fmaxf(fmaxf(lox - cA.x, cA.x - hix), 0.0f);
    float nyA = fmaxf(fmaxf(loy - cA.y, cA.y - hiy), 0.0f);
    float nzA = fmaxf(fmaxf(loz - cA.z, cA.z - hiz), 0.0f);
    bool pA = fmaf(nxA,nxA, fmaf(nyA,nyA, nzA*nzA)) <= thr;
    float nxB = fmaxf(fmaxf(lox - cB.x, cB.x - hix), 0.0f);
    float nyB = fmaxf(fmaxf(loy - cB.y, cB.y - hiy), 0.0f);
    float nzB = fmaxf(fmaxf(loz - cB.z, cB.z - hiz), 0.0f);
    bool pB = fmaf(nxB,nxB, fmaf(nyB,nyB, nzB*nzB)) <= thr;

    unsigned mlo = __ballot_sync(0xffffffffu, pA);      // colors 0..31
    unsigned mhi = __ballot_sync(0xffffffffu, pB);      // colors 32..63
    if (lane == 0) {
        g_mask32[cell] = make_uint2(mlo, mhi);
        int cnt = __popc(mlo) + __popc(mhi);
        // pure cell: unique candidate; every other color is > EPS worse in
        // squared distance for ALL points in the cell -> fp-safe shortcut.
        unsigned char b = 255;
        if (cnt == 1) b = (unsigned char)(mlo ? (__ffs(mlo) - 1) : (__ffs(mhi) + 31));
        g_pure[cell] = b;
    }
}

// ---------------- main kernel ----------------
extern __shared__ uint4 s_raw4[];

__device__ __forceinline__ void eval_cand(
    int k, float r, float g, float b,
    const float4* __restrict__ sp, float& bd, int& bi)
{
    float4 c = sp[k];
    float d = fmaf(r, c.x, fmaf(g, c.y, fmaf(b, c.z, c.w)));  // identical rounding to R1
    if (d < bd) { bd = d; bi = k; }                           // strict <: first-min wins
}

__device__ __forceinline__ int quantize_px(
    float r, float g, float b,
    const unsigned char* __restrict__ pure,
    const float4* __restrict__ sp)
{
    // *32 is a power-of-2 scale: exact cell assignment. fminf guards x==1.0.
    int ix = (int)fminf(r * 32.0f, 31.0f);
    int iy = (int)fminf(g * 32.0f, 31.0f);
    int iz = (int)fminf(b * 32.0f, 31.0f);
    int ci = (ix << 10) | (iy << 5) | iz;

    unsigned p = pure[ci];
    if (p != 255u) return (int)p;                       // ~75-80% of pixels

    uint2 rec = __ldg(&g_mask32[ci]);                   // L2-resident 256KB
    float bd = 3.4e38f; int bi = 0;
    unsigned m = rec.x;                                 // ascending k: tie-break order
    while (m) {
        int k = __ffs(m) - 1;
        m &= m - 1;
        eval_cand(k, r, g, b, sp, bd, bi);
    }
    m = rec.y;
    while (m) {
        int k = __ffs(m) + 31;
        m &= m - 1;
        eval_cand(k, r, g, b, sp, bd, bi);
    }
    return bi;
}

__global__ __launch_bounds__(TPB, 5) void color_reduce_kernel(
    const float* __restrict__ x,
    const float* __restrict__ pal,
    float* __restrict__ out)
{
    unsigned char* pure = (unsigned char*)s_raw4;            // 32KB
    float4* sp = (float4*)((char*)s_raw4 + NC2);             // {-2r,-2g,-2b,cc} 1KB
    float4* sc = sp + NC;                                    // raw colors      1KB

    int t = threadIdx.x;
    {   // stage pure LUT as 2048 uint4
        const uint4* src = (const uint4*)g_pure;
        #pragma unroll
        for (int i = t; i < NC2 / 16; i += TPB) s_raw4[i] = src[i];
    }
    if (t < NC) {
        float r = pal[3*t], g = pal[3*t+1], b = pal[3*t+2];
        sp[t] = make_float4(-2.0f*r, -2.0f*g, -2.0f*b, fmaf(r,r, fmaf(g,g, b*b)));
        sc[t] = make_float4(r, g, b, 0.0f);
    }
    __syncthreads();

    const int nquads = NB * HW / 4;                          // 524288
    for (int q = blockIdx.x * TPB + t; q < nquads; q += GRID * TPB) {
        int bIdx = q >> 16;
        int i    = (q & 65535) * 4;
        size_t base = (size_t)bIdx * (3 * HW) + i;

        float4 px = *(const float4*)(x + base);
        float4 py = *(const float4*)(x + base + HW);
        float4 pz = *(const float4*)(x + base + 2 * HW);

        int b0 = quantize_px(px.x, py.x, pz.x, pure, sp);
        int b1 = quantize_px(px.y, py.y, pz.y, pure, sp);
        int b2 = quantize_px(px.z, py.z, pz.z, pure, sp);
        int b3 = quantize_px(px.w, py.w, pz.w, pure, sp);

        float4 c0 = sc[b0], c1 = sc[b1], c2 = sc[b2], c3 = sc[b3];
        *(float4*)(out + base)          = make_float4(c0.x, c1.x, c2.x, c3.x);
        *(float4*)(out + base + HW)     = make_float4(c0.y, c1.y, c2.y, c3.y);
        *(float4*)(out + base + 2*HW)   = make_float4(c0.z, c1.z, c2.z, c3.z);
    }
}

extern "C" void kernel_launch(void* const* d_in, const int* in_sizes, int n_in,
                              void* d_out, int out_size)
{
    const float* x   = (const float*)d_in[0];
    const float* pal = (const float*)d_in[1];
    float*       out = (float*)d_out;

    const int smem_bytes = NC2 + 2 * NC * 16;     // 32768 + 2048 = 34816
    build_lut<<<(NC2 * 32) / TPB, TPB>>>(pal);    // warp per cell: 4096 blocks
    color_reduce_kernel<<<GRID, TPB, smem_bytes>>>(x, pal, out);
}

// round 15
// speedup vs baseline: 1.0036x; 1.0036x over previous
#include <cuda_runtime.h>

#define HW   262144            // 512*512
#define NB   8
#define NC   64
#define G2   32
#define NC2  (G2*G2*G2)        // 32768 cells
#define EPS  1e-4f
#define TPB  256
#define GRID 760               // persistent: 5 CTAs/SM * 152 SMs

// Per-cell: single winning color id (0..63) if the cell is "pure", else 255.
__device__ unsigned char g_pure[NC2];                   // 32KB
// Candidate bitmask for boundary cells (bit k => color k may win). L2-resident.
__device__ uint2 g_mask32[NC2];                         // 256KB

// ---------------- LUT build: thread per cell, 128 blocks ----------------
__global__ void build_lut(const float* __restrict__ pal)
{
    __shared__ float spal[3 * NC];                      // staged coalesced
    if (threadIdx.x < 3 * NC) spal[threadIdx.x] = pal[threadIdx.x];
    __syncthreads();

    int cell = blockIdx.x * TPB + threadIdx.x;
    int cx = (cell >> 10) & 31, cy = (cell >> 5) & 31, cz = cell & 31;
    const float inv = 1.0f / G2;
    float lox = cx * inv, hix = lox + inv;
    float loy = cy * inv, hiy = loy + inv;
    float loz = cz * inv, hiz = loz + inv;

    // thr = min over colors of (max sq distance from anywhere in the box)
    float thr = 3.4e38f;
    #pragma unroll 8
    for (int k = 0; k < NC; ++k) {
        float r = spal[3*k], g = spal[3*k+1], b = spal[3*k+2];
        float dx = fmaxf(r - lox, hix - r);
        float dy = fmaxf(g - loy, hiy - g);
        float dz = fmaxf(b - loz, hiz - b);
        thr = fminf(thr, fmaf(dx,dx, fmaf(dy,dy, dz*dz)));
    }
    thr += EPS;   // margin >> fp ordering noise in BOTH implementations

    // candidate mask: nearest-point box distance <= thr (ascending k)
    unsigned mlo = 0, mhi = 0;
    #pragma unroll 8
    for (int k = 0; k < NC; ++k) {
        float r = spal[3*k], g = spal[3*k+1], b = spal[3*k+2];
        float dx = fmaxf(fmaxf(lox - r, r - hix), 0.0f);
        float dy = fmaxf(fmaxf(loy - g, g - hiy), 0.0f);
        float dz = fmaxf(fmaxf(loz - b, b - hiz), 0.0f);
        if (fmaf(dx,dx, fmaf(dy,dy, dz*dz)) <= thr) {
            if (k < 32) mlo |= 1u << k; else mhi |= 1u << (k - 32);
        }
    }
    g_mask32[cell] = make_uint2(mlo, mhi);
    int cnt = __popc(mlo) + __popc(mhi);
    // pure cell: unique candidate -> every other color is > EPS worse for ALL
    // points in the cell; EPS dwarfs fp eval noise -> exact shortcut.
    unsigned char b = 255;
    if (cnt == 1) b = (unsigned char)(mlo ? (__ffs(mlo) - 1) : (__ffs(mhi) + 31));
    g_pure[cell] = b;
}

// ---------------- main kernel ----------------
extern __shared__ uint4 s_raw4[];

__device__ __forceinline__ void eval_cand(
    int k, float r, float g, float b,
    const float4* __restrict__ sp, float& bd, int& bi)
{
    float4 c = sp[k];
    float d = fmaf(r, c.x, fmaf(g, c.y, fmaf(b, c.z, c.w)));  // identical rounding to R1
    if (d < bd) { bd = d; bi = k; }                           // strict <: first-min wins
}

__device__ __forceinline__ int walk_mask(
    uint2 rec, float r, float g, float b, const float4* __restrict__ sp)
{
    float bd = 3.4e38f; int bi = 0;
    unsigned m = rec.x;                        // ascending k = tie-break order
    while (m) {
        int k = __ffs(m) - 1;
        m &= m - 1;
        eval_cand(k, r, g, b, sp, bd, bi);
    }
    m = rec.y;
    while (m) {
        int k = __ffs(m) + 31;
        m &= m - 1;
        eval_cand(k, r, g, b, sp, bd, bi);
    }
    return bi;
}

__global__ __launch_bounds__(TPB, 5) void color_reduce_kernel(
    const float* __restrict__ x,
    const float* __restrict__ pal,
    float* __restrict__ out)
{
    unsigned char* pure = (unsigned char*)s_raw4;            // 32KB
    float4* sp = (float4*)((char*)s_raw4 + NC2);             // {-2r,-2g,-2b,cc} 1KB
    float4* sc = sp + NC;                                    // raw colors      1KB

    int t = threadIdx.x;
    {   // stage pure LUT as 2048 uint4
        const uint4* src = (const uint4*)g_pure;
        #pragma unroll
        for (int i = t; i < NC2 / 16; i += TPB) s_raw4[i] = src[i];
    }
    if (t < NC) {
        float r = pal[3*t], g = pal[3*t+1], b = pal[3*t+2];
        sp[t] = make_float4(-2.0f*r, -2.0f*g, -2.0f*b, fmaf(r,r, fmaf(g,g, b*b)));
        sc[t] = make_float4(r, g, b, 0.0f);
    }
    __syncthreads();

    const int nquads = NB * HW / 4;                          // 524288
    for (int q = blockIdx.x * TPB + t; q < nquads; q += GRID * TPB) {
        int bIdx = q >> 16;
        int i    = (q & 65535) * 4;
        size_t base = (size_t)bIdx * (3 * HW) + i;

        float4 px = *(const float4*)(x + base);
        float4 py = *(const float4*)(x + base + HW);
        float4 pz = *(const float4*)(x + base + 2 * HW);

        float R[4] = {px.x, px.y, px.z, px.w};
        float Gc[4] = {py.x, py.y, py.z, py.w};
        float Bc[4] = {pz.x, pz.y, pz.z, pz.w};

        // Phase 1: cell ids + pure bytes (4 independent LDS.U8)
        int ci[4]; int idx[4];
        #pragma unroll
        for (int j = 0; j < 4; ++j) {
            int ix = (int)fminf(R[j]  * 32.0f, 31.0f);   // *32: exact pow-2 scale
            int iy = (int)fminf(Gc[j] * 32.0f, 31.0f);
            int iz = (int)fminf(Bc[j] * 32.0f, 31.0f);
            ci[j] = (ix << 10) | (iy << 5) | iz;
            idx[j] = (int)pure[ci[j]];
        }

        // Phase 2: issue ALL boundary mask loads first (MLP up to 4 on L2 path)
        uint2 rec[4];
        #pragma unroll
        for (int j = 0; j < 4; ++j)
            if (idx[j] == 255) rec[j] = __ldg(&g_mask32[ci[j]]);

        // Phase 3: walk masks
        #pragma unroll
        for (int j = 0; j < 4; ++j)
            if (idx[j] == 255) idx[j] = walk_mask(rec[j], R[j], Gc[j], Bc[j], sp);

        float4 c0 = sc[idx[0]], c1 = sc[idx[1]], c2 = sc[idx[2]], c3 = sc[idx[3]];
        *(float4*)(out + base)          = make_float4(c0.x, c1.x, c2.x, c3.x);
        *(float4*)(out + base + HW)     = make_float4(c0.y, c1.y, c2.y, c3.y);
        *(float4*)(out + base + 2*HW)   = make_float4(c0.z, c1.z, c2.z, c3.z);
    }
}

extern "C" void kernel_launch(void* const* d_in, const int* in_sizes, int n_in,
                              void* d_out, int out_size)
{
    const float* x   = (const float*)d_in[0];
    const float* pal = (const float*)d_in[1];
    float*       out = (float*)d_out;

    const int smem_bytes = NC2 + 2 * NC * 16;     // 32768 + 2048 = 34816
    build_lut<<<NC2 / TPB, TPB>>>(pal);           // thread per cell: 128 blocks
    color_reduce_kernel<<<GRID, TPB, smem_bytes>>>(x, pal, out);
}